// round 17
// baseline (speedup 1.0000x reference)
#include <cuda_runtime.h>
#include <cstdint>

// Problem constants (fixed by the reference)
#define BB 16
#define SS 2048
#define HH 1024

#define NPROD 128                  // u2 producer blocks (< wave-1 capacity 444)
#define ROWS_PER_BLK 16
#define ROW_BYTES (HH * 4)         // 4096 B per enc row
#define TILE_BYTES (ROWS_PER_BLK * ROW_BYTES)   // 65536

// Dynamic smem layout
#define SM_ENC   0                 // [0, 65536)  enc tile (TMA dst)
#define SM_SCR   65536             // [65536, 73728) producer partials (8KB), later su2 (4KB)
#define SM_MBAR  73728             // mbarrier (8B)
#define SM_TOTAL 73744

// Globals. Invariant: g_u2 == 0, g_done == 0 at entry of every kernel_launch
// (zero at module load; softmax_kernel restores both each call).
__device__ float g_u2[HH];
__device__ int   g_done;

__device__ __forceinline__ uint32_t smem_u32(const void* p) {
    uint32_t a;
    asm("{ .reg .u64 t; cvta.to.shared.u64 t, %1; cvt.u32.u64 %0, t; }"
        : "=r"(a) : "l"(p));
    return a;
}

// ---------------------------------------------------------------------------
// Fused u2 + scores kernel. grid 2048 x 512, 74KB dyn smem (3 CTA/SM).
//  1) every block: init mbarrier; tid0 issues 16x4KB cp.async.bulk of its enc
//     rows into smem (no registers held, overlaps everything below).
//  2) blocks 0..127: compute u2 = v^T @ W[:,H:2H] slice (64 rows x 128 cols),
//     REDG-atomic into g_u2, ONE threadfence (tid0), bump g_done.
//  3) all blocks: tid0 polls g_done (wave-1 consumers wait under their own
//     in-flight TMA; later waves pass immediately), stage u2 via __ldcg,
//     wait the TMA mbarrier, dot 16 rows from smem, store scores.
// ---------------------------------------------------------------------------
__global__ __launch_bounds__(512) void fused_kernel(
    const float* __restrict__ attn_w,  // [H, 2H] row-major
    const float* __restrict__ v,       // [1, H]
    const float* __restrict__ enc,     // [B, S, H]
    float* __restrict__ out)           // [B*S] scores (in d_out)
{
    extern __shared__ char smem[];
    const uint32_t sbase = smem_u32(smem);
    const uint32_t mbar  = sbase + SM_MBAR;

    const int tid  = threadIdx.x;
    const int warp = tid >> 5;          // 0..15
    const int lane = tid & 31;
    const int bid  = blockIdx.x;

    // ---- 1) mbarrier init + TMA prefetch of this block's 16 enc rows ----
    if (tid == 0) {
        asm volatile("mbarrier.init.shared.b64 [%0], %1;" :: "r"(mbar), "r"(1));
        asm volatile("fence.proxy.async.shared::cta;" ::: "memory");
    }
    __syncthreads();
    if (tid == 0) {
        asm volatile("mbarrier.arrive.expect_tx.shared.b64 _, [%0], %1;"
                     :: "r"(mbar), "r"((uint32_t)TILE_BYTES));
        const char* src = reinterpret_cast<const char*>(enc)
                        + (size_t)bid * TILE_BYTES;
#pragma unroll
        for (int r = 0; r < ROWS_PER_BLK; ++r) {
            asm volatile(
                "cp.async.bulk.shared::cta.global.mbarrier::complete_tx::bytes "
                "[%0], [%1], %2, [%3];"
                :: "r"(sbase + SM_ENC + r * ROW_BYTES),
                   "l"(src + (size_t)r * ROW_BYTES),
                   "r"((uint32_t)ROW_BYTES), "r"(mbar)
                : "memory");
        }
    }

    // ---- 2) producers: u2 slice ----
    if (bid < NPROD) {
        float4* part = reinterpret_cast<float4*>(smem + SM_SCR); // [16][32]
        const int j0 = (bid & 7) * 128;        // 8 column tiles of 128 floats
        const int h0 = (bid >> 3) * 64;        // 16 chunks of 64 rows
        const float4* base =
            reinterpret_cast<const float4*>(attn_w + HH + j0) + lane;
        const size_t rs = (2 * HH) / 4;        // float4 stride per row

        float4 acc = make_float4(0.f, 0.f, 0.f, 0.f);
#pragma unroll
        for (int i = 0; i < 4; ++i) {
            const int h = h0 + warp + i * 16;
            const float vv = __ldg(v + h);
            const float4 w4 = __ldg(base + (size_t)h * rs);
            acc.x += vv * w4.x; acc.y += vv * w4.y;
            acc.z += vv * w4.z; acc.w += vv * w4.w;
        }
        part[warp * 32 + lane] = acc;
        __syncthreads();
        if (warp == 0) {
            float4 s = part[lane];
#pragma unroll
            for (int w = 1; w < 16; ++w) {
                const float4 p = part[w * 32 + lane];
                s.x += p.x; s.y += p.y; s.z += p.z; s.w += p.w;
            }
            float* dst = g_u2 + j0 + lane * 4;
            atomicAdd(dst + 0, s.x);
            atomicAdd(dst + 1, s.y);
            atomicAdd(dst + 2, s.z);
            atomicAdd(dst + 3, s.w);
        }
        __syncthreads();
        if (tid == 0) { __threadfence(); atomicAdd(&g_done, 1); }
    }

    // ---- 3) wait for u2 (TMA already in flight underneath) ----
    if (tid == 0) {
        while (*((volatile int*)&g_done) != NPROD)
            __nanosleep(128);
    }
    __syncthreads();

    // stage u2 from L2 (atomics live in L2; __ldcg is coherent there)
    float4* su2 = reinterpret_cast<float4*>(smem + SM_SCR);   // 256 x float4
    if (tid < HH / 4)
        su2[tid] = __ldcg(reinterpret_cast<const float4*>(g_u2) + tid);

    // wait for this block's enc tile
    {
        uint32_t done;
        do {
            asm volatile(
                "{ .reg .pred p; mbarrier.try_wait.parity.shared.b64 p, [%1], 0; "
                "selp.b32 %0, 1, 0, p; }"
                : "=r"(done) : "r"(mbar) : "memory");
        } while (!done);
    }
    __syncthreads();

    // ---- dot: score[row] = enc_row . u2, enc from smem ----
    const float4* erow = reinterpret_cast<const float4*>(smem + SM_ENC + warp * ROW_BYTES);
    float acc = 0.f;
#pragma unroll
    for (int it = 0; it < 8; ++it) {
        const float4 ev = erow[it * 32 + lane];
        const float4 uv = su2[it * 32 + lane];
        acc += ev.x * uv.x + ev.y * uv.y + ev.z * uv.z + ev.w * uv.w;
    }
#pragma unroll
    for (int m = 16; m; m >>= 1)
        acc += __shfl_xor_sync(0xffffffffu, acc, m);
    if (lane == 0) out[bid * ROWS_PER_BLK + warp] = acc;
}

// ---------------------------------------------------------------------------
// Softmax: in-place over S=2048 per batch, 16 blocks x 1024 threads (float2).
// Block 0 restores g_u2 == 0 and g_done == 0 for the next graph replay.
// ---------------------------------------------------------------------------
__global__ __launch_bounds__(1024) void softmax_kernel(float* __restrict__ out)
{
    __shared__ float red[32];
    const int tid  = threadIdx.x;
    const int warp = tid >> 5;           // 0..31
    const int lane = tid & 31;

    if (blockIdx.x == 0) {
        if (tid < HH / 4)
            reinterpret_cast<float4*>(g_u2)[tid] = make_float4(0.f, 0.f, 0.f, 0.f);
        if (tid == 0) g_done = 0;
    }

    float2* po = reinterpret_cast<float2*>(out + (size_t)blockIdx.x * SS);
    float2 x = po[tid];

    // block max
    float mx = fmaxf(x.x, x.y);
#pragma unroll
    for (int m = 16; m; m >>= 1)
        mx = fmaxf(mx, __shfl_xor_sync(0xffffffffu, mx, m));
    if (lane == 0) red[warp] = mx;
    __syncthreads();
    if (warp == 0) {
        float t = red[lane];
#pragma unroll
        for (int m = 16; m; m >>= 1)
            t = fmaxf(t, __shfl_xor_sync(0xffffffffu, t, m));
        red[lane] = t;
    }
    __syncthreads();
    const float bmax = red[0];

    // exp + block sum
    x.x = __expf(x.x - bmax);
    x.y = __expf(x.y - bmax);
    float s = x.x + x.y;
#pragma unroll
    for (int m = 16; m; m >>= 1)
        s += __shfl_xor_sync(0xffffffffu, s, m);
    __syncthreads();
    if (lane == 0) red[warp] = s;
    __syncthreads();
    if (warp == 0) {
        float t = red[lane];
#pragma unroll
        for (int m = 16; m; m >>= 1)
            t += __shfl_xor_sync(0xffffffffu, t, m);
        red[lane] = t;
    }
    __syncthreads();
    const float inv = 1.0f / red[0];

    x.x *= inv; x.y *= inv;
    po[tid] = x;
}

// ---------------------------------------------------------------------------
// Inputs (metadata order): hidden [B,1,H], encoder_outputs [B,S,H],
//                          attn_w [H,2H], attn_b [H], v [1,H]
// hidden and attn_b are provably unused (softmax shift invariance folds them
// into a per-row constant).
// Output: [B,1,S] float32.
// ---------------------------------------------------------------------------
extern "C" void kernel_launch(void* const* d_in, const int* in_sizes, int n_in,
                              void* d_out, int out_size)
{
    const float* enc    = (const float*)d_in[1];
    const float* attn_w = (const float*)d_in[2];
    const float* v      = (const float*)d_in[4];
    float* out = (float*)d_out;

    static bool configured = false;
    if (!configured) {
        cudaFuncSetAttribute(fused_kernel,
                             cudaFuncAttributeMaxDynamicSharedMemorySize, SM_TOTAL);
        configured = true;
    }

    fused_kernel<<<(BB * SS) / ROWS_PER_BLK, 512, SM_TOTAL>>>(attn_w, v, enc, out);
    softmax_kernel<<<BB, 1024>>>(out);
}